// round 11
// baseline (speedup 1.0000x reference)
#include <cuda_runtime.h>
#include <cuda_fp16.h>
#include <math.h>

#define OUT_H 7
#define OUT_W 7
#define NBINS 49
#define NSAMP 196
#define C_ 256
#define H_ 200
#define W_ 200
#define HW (H_*W_)
#define SPATIAL_SCALE 0.25f

// NHWC fp16 scratch: [B=2][H=200][W=200][C=256]  (41 MB)
__device__ __half g_nhwc[2 * H_ * W_ * C_];

// ---------------------------------------------------------------------------
// Kernel 1: NCHW fp32 -> NHWC fp16 transpose (round-10 config, at DRAM roof).
// Tile: 64 x-positions × 64 channels. Block (32,8).
// ---------------------------------------------------------------------------
__global__ __launch_bounds__(256)
void transpose_kernel(const float* __restrict__ feat)
{
    __shared__ __half2 s2[64][33];     // [x][cpair]

    const int x0 = blockIdx.x * 64;
    const int by = blockIdx.y;          // b*H + y
    const int b  = by / H_;
    const int y  = by % H_;
    const int c0 = blockIdx.z * 64;
    const int tx = threadIdx.x;
    const int ty = threadIdx.y;

    const float* src = feat + ((size_t)(b * C_ + c0) * H_ + y) * W_;
    const int x = x0 + 2 * tx;          // thread covers x, x+1

    #pragma unroll
    for (int i = 0; i < 4; ++i) {
        int p = ty + 8 * i;             // channel pair 0..31
        if (x + 1 < W_) {
            float2 fa = *(const float2*)(src + (size_t)(2 * p    ) * HW + x);
            float2 fb = *(const float2*)(src + (size_t)(2 * p + 1) * HW + x);
            s2[2 * tx    ][p] = __floats2half2_rn(fa.x, fb.x);
            s2[2 * tx + 1][p] = __floats2half2_rn(fa.y, fb.y);
        } else if (x < W_) {
            float fa = src[(size_t)(2 * p    ) * HW + x];
            float fb = src[(size_t)(2 * p + 1) * HW + x];
            s2[2 * tx][p] = __floats2half2_rn(fa, fb);
        }
    }
    __syncthreads();

    __half* dst = g_nhwc + ((size_t)(b * H_ + y) * W_ + x0) * C_ + c0;
    #pragma unroll
    for (int i = 0; i < 8; ++i) {
        int xr = ty + 8 * i;            // 0..63
        if (x0 + xr < W_)
            *(__half2*)(dst + (size_t)xr * C_ + 2 * tx) = s2[xr][tx];
    }
}

// ---------------------------------------------------------------------------
// Kernel 2: gather. Block = (roi, channel-half). 256 threads, 8 warps.
// Round-7 hot loop verbatim (lane = 4 contiguous channels, LDG.64/corner,
// HFMA2 combine, per-sample fp32 widening). ONLY change vs round 10:
// s_out staged as [128][25] over TWO bin passes (0-24, 25-48) -> smem
// 31.4KB -> 18.4KB, tripling L1D carveout (40KB -> ~115KB).
// Swizzle c' = (c&3)*32 + (c>>2): STS lane stride 25 (odd, conflict-free),
// flush reads consecutive (conflict-free).
// ---------------------------------------------------------------------------
#define PB 25   // bins in pass 0 (pass 1 has 24)

__global__ __launch_bounds__(256, 6)
void roi_gather_kernel(const float* __restrict__ rois,
                       float* __restrict__ out)
{
    __shared__ int   s_base[NSAMP];   // element index of corner v1 (c=0)
    __shared__ int   s_dxe [NSAMP];   // dx * C_
    __shared__ int   s_dye [NSAMP];   // dy * W_ * C_
    __shared__ uint4 s_w   [NSAMP];   // 4 corner weights, each as dup half2
    __shared__ float s_out [128 * PB];

    const int r = blockIdx.x >> 1;
    const int h = blockIdx.x & 1;
    const int t = threadIdx.x;
    const int w = t >> 5;
    const int l = t & 31;
    const __half* __restrict__ g = g_nhwc;

    if (t < NSAMP) {
        const float* rp = rois + r * 6;
        float cx = rp[1] * SPATIAL_SCALE - 0.5f;
        float cy = rp[2] * SPATIAL_SCALE - 0.5f;
        float rw = rp[3] * SPATIAL_SCALE;
        float rh = rp[4] * SPATIAL_SCALE;
        float sn, cs;
        sincosf(rp[5], &sn, &cs);
        int bofs = (int)rp[0] * HW;

        int bin = t >> 2;
        int sub = t & 3;
        int iy = sub >> 1, ix = sub & 1;
        int ph = bin / OUT_W;
        int pw = bin - ph * OUT_W;

        float bin_h = rh * (1.0f / OUT_H);
        float bin_w = rw * (1.0f / OUT_W);
        float yy = -0.5f * rh + ((float)ph + ((float)iy + 0.5f) * 0.5f) * bin_h;
        float xx = -0.5f * rw + ((float)pw + ((float)ix + 0.5f) * 0.5f) * bin_w;

        float x = yy * sn + xx * cs + cx;
        float y = yy * cs - xx * sn + cy;

        bool valid = (y > -1.0f) && (y < (float)H_) && (x > -1.0f) && (x < (float)W_);
        y = fmaxf(y, 0.0f);
        x = fmaxf(x, 0.0f);

        int yl = (int)floorf(y);
        int xl = (int)floorf(x);
        float ly, lx;
        int dy, dx;
        if (yl >= H_ - 1) { yl = H_ - 1; dy = 0; ly = 0.0f; }
        else              { dy = 1;      ly = y - (float)yl; }
        if (xl >= W_ - 1) { xl = W_ - 1; dx = 0; lx = 0.0f; }
        else              { dx = 1;      lx = x - (float)xl; }
        float hy = 1.0f - ly, hx = 1.0f - lx;
        float sc = valid ? 0.25f : 0.0f;

        s_base[t] = (bofs + yl * W_ + xl) * C_;
        s_dxe [t] = dx * C_;
        s_dye [t] = dy * (W_ * C_);

        __half2 w1 = __half2half2(__float2half(sc * hy * hx));
        __half2 w2 = __half2half2(__float2half(sc * hy * lx));
        __half2 w3 = __half2half2(__float2half(sc * ly * hx));
        __half2 w4 = __half2half2(__float2half(sc * ly * lx));
        uint4 wp;
        wp.x = *(unsigned*)&w1; wp.y = *(unsigned*)&w2;
        wp.z = *(unsigned*)&w3; wp.w = *(unsigned*)&w4;
        s_w[t] = wp;
    }
    __syncthreads();

    const int cofs = h * 128 + 4 * l;    // global channel of lane's first ch
    float* op = out + (size_t)r * (C_ * NBINS) + h * (128 * NBINS);

    #pragma unroll 1
    for (int pass = 0; pass < 2; ++pass) {
        const int bin0 = pass * PB;               // 0 or 25
        const int nb   = pass ? (NBINS - PB) : PB; // 25 or 24
        float* so = s_out + l * nb;               // c' = j*32+l rows

        #pragma unroll 1
        for (int bl = w; bl < nb; bl += 8) {
            const int bin = bin0 + bl;
            float a0 = 0.f, a1 = 0.f, a2 = 0.f, a3 = 0.f;

            #pragma unroll
            for (int s = 0; s < 4; ++s) {
                int mi  = bin * 4 + s;
                int A   = s_base[mi] + cofs;
                int dxe = s_dxe[mi];
                int dye = s_dye[mi];
                uint4 wp = s_w[mi];
                __half2 w1 = *(__half2*)&wp.x, w2 = *(__half2*)&wp.y;
                __half2 w3 = *(__half2*)&wp.z, w4 = *(__half2*)&wp.w;

                uint2 q1 = *(const uint2*)(g + A);
                uint2 q2 = *(const uint2*)(g + A + dxe);
                uint2 q3 = *(const uint2*)(g + A + dye);
                uint2 q4 = *(const uint2*)(g + A + dye + dxe);

                __half2 lo = __hmul2(*(__half2*)&q1.x, w1);
                lo = __hfma2(*(__half2*)&q2.x, w2, lo);
                lo = __hfma2(*(__half2*)&q3.x, w3, lo);
                lo = __hfma2(*(__half2*)&q4.x, w4, lo);
                __half2 hi = __hmul2(*(__half2*)&q1.y, w1);
                hi = __hfma2(*(__half2*)&q2.y, w2, hi);
                hi = __hfma2(*(__half2*)&q3.y, w3, hi);
                hi = __hfma2(*(__half2*)&q4.y, w4, hi);

                float2 flo = __half22float2(lo);
                float2 fhi = __half22float2(hi);
                a0 += flo.x; a1 += flo.y; a2 += fhi.x; a3 += fhi.y;
            }
            so[0 * 32 * nb + bl] = a0;
            so[1 * 32 * nb + bl] = a1;
            so[2 * 32 * nb + bl] = a2;
            so[3 * 32 * nb + bl] = a3;
        }
        __syncthreads();

        // flush this pass: 128*nb floats; invert channel swizzle.
        const int total = 128 * nb;               // 3200 or 3072
        #pragma unroll 1
        for (int idx = t; idx < total; idx += 256) {
            int c  = idx / nb;
            int bl = idx - c * nb;
            op[c * NBINS + bin0 + bl] =
                s_out[(((c & 3) * 32 + (c >> 2)) * nb) + bl];
        }
        __syncthreads();
    }
}

extern "C" void kernel_launch(void* const* d_in, const int* in_sizes, int n_in,
                              void* d_out, int out_size)
{
    const float* feat = (const float*)d_in[0];   // [2,256,200,200] f32
    const float* rois = (const float*)d_in[1];   // [1000,6] f32
    float* out = (float*)d_out;                  // [1000,256,7,7] f32

    int R = in_sizes[1] / 6;

    dim3 tgrid((W_ + 63) / 64, 2 * H_, C_ / 64);
    dim3 tblk(32, 8);
    transpose_kernel<<<tgrid, tblk>>>(feat);

    roi_gather_kernel<<<R * 2, 256>>>(rois, out);
}

// round 12
// speedup vs baseline: 1.1866x; 1.1866x over previous
#include <cuda_runtime.h>
#include <cuda_fp16.h>
#include <math.h>

#define OUT_H 7
#define OUT_W 7
#define NBINS 49
#define NSAMP 196
#define C_ 256
#define H_ 200
#define W_ 200
#define HW (H_*W_)
#define SPATIAL_SCALE 0.25f

// NHWC fp16 scratch: [B=2][H=200][W=200][C=256]  (41 MB)
__device__ __half g_nhwc[2 * H_ * W_ * C_];

// ---------------------------------------------------------------------------
// Kernel 1: NCHW fp32 -> NHWC fp16 transpose (round-10 config, DRAM roof).
// Feature loads use __ldcs (evict-first): features are single-use, keep L2
// free so the NHWC output stays resident for the gather kernel.
// ---------------------------------------------------------------------------
__global__ __launch_bounds__(256)
void transpose_kernel(const float* __restrict__ feat)
{
    __shared__ __half2 s2[64][33];     // [x][cpair]

    const int x0 = blockIdx.x * 64;
    const int by = blockIdx.y;          // b*H + y
    const int b  = by / H_;
    const int y  = by % H_;
    const int c0 = blockIdx.z * 64;
    const int tx = threadIdx.x;
    const int ty = threadIdx.y;

    const float* src = feat + ((size_t)(b * C_ + c0) * H_ + y) * W_;
    const int x = x0 + 2 * tx;          // thread covers x, x+1

    #pragma unroll
    for (int i = 0; i < 4; ++i) {
        int p = ty + 8 * i;             // channel pair 0..31
        if (x + 1 < W_) {
            float2 fa = __ldcs((const float2*)(src + (size_t)(2 * p    ) * HW + x));
            float2 fb = __ldcs((const float2*)(src + (size_t)(2 * p + 1) * HW + x));
            s2[2 * tx    ][p] = __floats2half2_rn(fa.x, fb.x);
            s2[2 * tx + 1][p] = __floats2half2_rn(fa.y, fb.y);
        } else if (x < W_) {
            float fa = __ldcs(src + (size_t)(2 * p    ) * HW + x);
            float fb = __ldcs(src + (size_t)(2 * p + 1) * HW + x);
            s2[2 * tx][p] = __floats2half2_rn(fa, fb);
        }
    }
    __syncthreads();

    __half* dst = g_nhwc + ((size_t)(b * H_ + y) * W_ + x0) * C_ + c0;
    #pragma unroll
    for (int i = 0; i < 8; ++i) {
        int xr = ty + 8 * i;            // 0..63
        if (x0 + xr < W_)
            *(__half2*)(dst + (size_t)xr * C_ + 2 * tx) = s2[xr][tx];
    }
}

// ---------------------------------------------------------------------------
// Kernel 2: gather (round-10 proven config, verbatim). Block = (roi, ch-half).
// 256 threads, 8 warps. Warp owns a bin; lane l owns 4 contiguous channels
// (LDG.64 per corner). HFMA2 bilinear combine, widen to fp32 per sample
// (4 independent chains). s_out swizzle c' = (c&3)*32 + (c>>2).
// ---------------------------------------------------------------------------
__global__ __launch_bounds__(256, 6)
void roi_gather_kernel(const float* __restrict__ rois,
                       float* __restrict__ out)
{
    __shared__ int   s_base[NSAMP];   // element index of corner v1 (c=0)
    __shared__ int   s_dxe [NSAMP];   // dx * C_
    __shared__ int   s_dye [NSAMP];   // dy * W_ * C_
    __shared__ uint4 s_w   [NSAMP];   // 4 corner weights, each as dup half2
    __shared__ float s_out [128 * NBINS];

    const int r = blockIdx.x >> 1;
    const int h = blockIdx.x & 1;
    const int t = threadIdx.x;
    const int w = t >> 5;
    const int l = t & 31;
    const __half* __restrict__ g = g_nhwc;

    if (t < NSAMP) {
        const float* rp = rois + r * 6;
        float cx = rp[1] * SPATIAL_SCALE - 0.5f;
        float cy = rp[2] * SPATIAL_SCALE - 0.5f;
        float rw = rp[3] * SPATIAL_SCALE;
        float rh = rp[4] * SPATIAL_SCALE;
        float sn, cs;
        sincosf(rp[5], &sn, &cs);
        int bofs = (int)rp[0] * HW;

        int bin = t >> 2;
        int sub = t & 3;
        int iy = sub >> 1, ix = sub & 1;
        int ph = bin / OUT_W;
        int pw = bin - ph * OUT_W;

        float bin_h = rh * (1.0f / OUT_H);
        float bin_w = rw * (1.0f / OUT_W);
        float yy = -0.5f * rh + ((float)ph + ((float)iy + 0.5f) * 0.5f) * bin_h;
        float xx = -0.5f * rw + ((float)pw + ((float)ix + 0.5f) * 0.5f) * bin_w;

        float x = yy * sn + xx * cs + cx;
        float y = yy * cs - xx * sn + cy;

        bool valid = (y > -1.0f) && (y < (float)H_) && (x > -1.0f) && (x < (float)W_);
        y = fmaxf(y, 0.0f);
        x = fmaxf(x, 0.0f);

        int yl = (int)floorf(y);
        int xl = (int)floorf(x);
        float ly, lx;
        int dy, dx;
        if (yl >= H_ - 1) { yl = H_ - 1; dy = 0; ly = 0.0f; }
        else              { dy = 1;      ly = y - (float)yl; }
        if (xl >= W_ - 1) { xl = W_ - 1; dx = 0; lx = 0.0f; }
        else              { dx = 1;      lx = x - (float)xl; }
        float hy = 1.0f - ly, hx = 1.0f - lx;
        float sc = valid ? 0.25f : 0.0f;

        s_base[t] = (bofs + yl * W_ + xl) * C_;
        s_dxe [t] = dx * C_;
        s_dye [t] = dy * (W_ * C_);

        __half2 w1 = __half2half2(__float2half(sc * hy * hx));
        __half2 w2 = __half2half2(__float2half(sc * hy * lx));
        __half2 w3 = __half2half2(__float2half(sc * ly * hx));
        __half2 w4 = __half2half2(__float2half(sc * ly * lx));
        uint4 wp;
        wp.x = *(unsigned*)&w1; wp.y = *(unsigned*)&w2;
        wp.z = *(unsigned*)&w3; wp.w = *(unsigned*)&w4;
        s_w[t] = wp;
    }
    __syncthreads();

    const int cofs = h * 128 + 4 * l;    // global channel of lane's first ch
    float* so = s_out + l * NBINS;       // + j*32*NBINS + bin  (c' = j*32+l)

    #pragma unroll 1
    for (int bin = w; bin < NBINS; bin += 8) {
        float a0 = 0.f, a1 = 0.f, a2 = 0.f, a3 = 0.f;

        #pragma unroll
        for (int s = 0; s < 4; ++s) {
            int mi  = bin * 4 + s;
            int A   = s_base[mi] + cofs;
            int dxe = s_dxe[mi];
            int dye = s_dye[mi];
            uint4 wp = s_w[mi];
            __half2 w1 = *(__half2*)&wp.x, w2 = *(__half2*)&wp.y;
            __half2 w3 = *(__half2*)&wp.z, w4 = *(__half2*)&wp.w;

            uint2 q1 = *(const uint2*)(g + A);
            uint2 q2 = *(const uint2*)(g + A + dxe);
            uint2 q3 = *(const uint2*)(g + A + dye);
            uint2 q4 = *(const uint2*)(g + A + dye + dxe);

            __half2 lo = __hmul2(*(__half2*)&q1.x, w1);
            lo = __hfma2(*(__half2*)&q2.x, w2, lo);
            lo = __hfma2(*(__half2*)&q3.x, w3, lo);
            lo = __hfma2(*(__half2*)&q4.x, w4, lo);
            __half2 hi = __hmul2(*(__half2*)&q1.y, w1);
            hi = __hfma2(*(__half2*)&q2.y, w2, hi);
            hi = __hfma2(*(__half2*)&q3.y, w3, hi);
            hi = __hfma2(*(__half2*)&q4.y, w4, hi);

            float2 flo = __half22float2(lo);
            float2 fhi = __half22float2(hi);
            a0 += flo.x; a1 += flo.y; a2 += fhi.x; a3 += fhi.y;
        }
        so[0 * 32 * NBINS + bin] = a0;
        so[1 * 32 * NBINS + bin] = a1;
        so[2 * 32 * NBINS + bin] = a2;
        so[3 * 32 * NBINS + bin] = a3;
    }
    __syncthreads();

    // flush 128*49 = 6272 floats, coalesced; invert channel swizzle.
    float* op = out + (size_t)r * (C_ * NBINS) + h * (128 * NBINS);
    #pragma unroll
    for (int j = 0; j < 25; ++j) {
        int idx = j * 256 + t;
        if (j < 24 || t < 128) {
            int c   = idx / NBINS;
            int bin = idx - c * NBINS;
            op[idx] = s_out[((c & 3) * 32 + (c >> 2)) * NBINS + bin];
        }
    }
}

extern "C" void kernel_launch(void* const* d_in, const int* in_sizes, int n_in,
                              void* d_out, int out_size)
{
    const float* feat = (const float*)d_in[0];   // [2,256,200,200] f32
    const float* rois = (const float*)d_in[1];   // [1000,6] f32
    float* out = (float*)d_out;                  // [1000,256,7,7] f32

    int R = in_sizes[1] / 6;

    dim3 tgrid((W_ + 63) / 64, 2 * H_, C_ / 64);
    dim3 tblk(32, 8);
    transpose_kernel<<<tgrid, tblk>>>(feat);

    roi_gather_kernel<<<R * 2, 256>>>(rois, out);
}

// round 13
// speedup vs baseline: 1.2710x; 1.0712x over previous
#include <cuda_runtime.h>
#include <cuda_fp16.h>
#include <math.h>

#define OUT_H 7
#define OUT_W 7
#define NBINS 49
#define NSAMP 196
#define C_ 256
#define H_ 200
#define W_ 200
#define HW (H_*W_)
#define SPATIAL_SCALE 0.25f

// NHWC fp16 scratch: [B=2][H=200][W=200][C=256]  (41 MB)
__device__ __half g_nhwc[2 * H_ * W_ * C_];

// ---------------------------------------------------------------------------
// Kernel 1: NCHW fp32 -> NHWC fp16 transpose (round-12 config, DRAM roof).
// ---------------------------------------------------------------------------
__global__ __launch_bounds__(256)
void transpose_kernel(const float* __restrict__ feat)
{
    __shared__ __half2 s2[64][33];     // [x][cpair]

    const int x0 = blockIdx.x * 64;
    const int by = blockIdx.y;          // b*H + y
    const int b  = by / H_;
    const int y  = by % H_;
    const int c0 = blockIdx.z * 64;
    const int tx = threadIdx.x;
    const int ty = threadIdx.y;

    const float* src = feat + ((size_t)(b * C_ + c0) * H_ + y) * W_;
    const int x = x0 + 2 * tx;          // thread covers x, x+1

    #pragma unroll
    for (int i = 0; i < 4; ++i) {
        int p = ty + 8 * i;             // channel pair 0..31
        if (x + 1 < W_) {
            float2 fa = __ldcs((const float2*)(src + (size_t)(2 * p    ) * HW + x));
            float2 fb = __ldcs((const float2*)(src + (size_t)(2 * p + 1) * HW + x));
            s2[2 * tx    ][p] = __floats2half2_rn(fa.x, fb.x);
            s2[2 * tx + 1][p] = __floats2half2_rn(fa.y, fb.y);
        } else if (x < W_) {
            float fa = __ldcs(src + (size_t)(2 * p    ) * HW + x);
            float fb = __ldcs(src + (size_t)(2 * p + 1) * HW + x);
            s2[2 * tx][p] = __floats2half2_rn(fa, fb);
        }
    }
    __syncthreads();

    __half* dst = g_nhwc + ((size_t)(b * H_ + y) * W_ + x0) * C_ + c0;
    #pragma unroll
    for (int i = 0; i < 8; ++i) {
        int xr = ty + 8 * i;            // 0..63
        if (x0 + xr < W_)
            *(__half2*)(dst + (size_t)xr * C_ + 2 * tx) = s2[xr][tx];
    }
}

// ---------------------------------------------------------------------------
// Kernel 2: gather. Block = (roi, channel-half). 256 threads, 8 warps.
// 2-BIN ILP: each warp processes bins {16k+2w, 16k+2w+1} per iteration
// (k=0..2 covers bins 0..47; bin 48 = warp-0 epilogue). 32 independent
// LDG.64 in flight per warp. Numerics identical to round 12 (HFMA2 combine,
// per-sample fp32 widening). s_out swizzle c' = (c&3)*32 + (c>>2).
// ---------------------------------------------------------------------------
__device__ __forceinline__ void gather_bin(
    const __half* __restrict__ g,
    const int* s_base, const int* s_dxe, const int* s_dye, const uint4* s_w,
    int bin, int cofs, float& a0, float& a1, float& a2, float& a3)
{
    a0 = 0.f; a1 = 0.f; a2 = 0.f; a3 = 0.f;
    #pragma unroll
    for (int s = 0; s < 4; ++s) {
        int mi  = bin * 4 + s;
        int A   = s_base[mi] + cofs;
        int dxe = s_dxe[mi];
        int dye = s_dye[mi];
        uint4 wp = s_w[mi];
        __half2 w1 = *(__half2*)&wp.x, w2 = *(__half2*)&wp.y;
        __half2 w3 = *(__half2*)&wp.z, w4 = *(__half2*)&wp.w;

        uint2 q1 = *(const uint2*)(g + A);
        uint2 q2 = *(const uint2*)(g + A + dxe);
        uint2 q3 = *(const uint2*)(g + A + dye);
        uint2 q4 = *(const uint2*)(g + A + dye + dxe);

        __half2 lo = __hmul2(*(__half2*)&q1.x, w1);
        lo = __hfma2(*(__half2*)&q2.x, w2, lo);
        lo = __hfma2(*(__half2*)&q3.x, w3, lo);
        lo = __hfma2(*(__half2*)&q4.x, w4, lo);
        __half2 hi = __hmul2(*(__half2*)&q1.y, w1);
        hi = __hfma2(*(__half2*)&q2.y, w2, hi);
        hi = __hfma2(*(__half2*)&q3.y, w3, hi);
        hi = __hfma2(*(__half2*)&q4.y, w4, hi);

        float2 flo = __half22float2(lo);
        float2 fhi = __half22float2(hi);
        a0 += flo.x; a1 += flo.y; a2 += fhi.x; a3 += fhi.y;
    }
}

__global__ __launch_bounds__(256, 4)
void roi_gather_kernel(const float* __restrict__ rois,
                       float* __restrict__ out)
{
    __shared__ int   s_base[NSAMP];   // element index of corner v1 (c=0)
    __shared__ int   s_dxe [NSAMP];   // dx * C_
    __shared__ int   s_dye [NSAMP];   // dy * W_ * C_
    __shared__ uint4 s_w   [NSAMP];   // 4 corner weights, each as dup half2
    __shared__ float s_out [128 * NBINS];

    const int r = blockIdx.x >> 1;
    const int h = blockIdx.x & 1;
    const int t = threadIdx.x;
    const int w = t >> 5;
    const int l = t & 31;
    const __half* __restrict__ g = g_nhwc;

    if (t < NSAMP) {
        const float* rp = rois + r * 6;
        float cx = rp[1] * SPATIAL_SCALE - 0.5f;
        float cy = rp[2] * SPATIAL_SCALE - 0.5f;
        float rw = rp[3] * SPATIAL_SCALE;
        float rh = rp[4] * SPATIAL_SCALE;
        float sn, cs;
        sincosf(rp[5], &sn, &cs);
        int bofs = (int)rp[0] * HW;

        int bin = t >> 2;
        int sub = t & 3;
        int iy = sub >> 1, ix = sub & 1;
        int ph = bin / OUT_W;
        int pw = bin - ph * OUT_W;

        float bin_h = rh * (1.0f / OUT_H);
        float bin_w = rw * (1.0f / OUT_W);
        float yy = -0.5f * rh + ((float)ph + ((float)iy + 0.5f) * 0.5f) * bin_h;
        float xx = -0.5f * rw + ((float)pw + ((float)ix + 0.5f) * 0.5f) * bin_w;

        float x = yy * sn + xx * cs + cx;
        float y = yy * cs - xx * sn + cy;

        bool valid = (y > -1.0f) && (y < (float)H_) && (x > -1.0f) && (x < (float)W_);
        y = fmaxf(y, 0.0f);
        x = fmaxf(x, 0.0f);

        int yl = (int)floorf(y);
        int xl = (int)floorf(x);
        float ly, lx;
        int dy, dx;
        if (yl >= H_ - 1) { yl = H_ - 1; dy = 0; ly = 0.0f; }
        else              { dy = 1;      ly = y - (float)yl; }
        if (xl >= W_ - 1) { xl = W_ - 1; dx = 0; lx = 0.0f; }
        else              { dx = 1;      lx = x - (float)xl; }
        float hy = 1.0f - ly, hx = 1.0f - lx;
        float sc = valid ? 0.25f : 0.0f;

        s_base[t] = (bofs + yl * W_ + xl) * C_;
        s_dxe [t] = dx * C_;
        s_dye [t] = dy * (W_ * C_);

        __half2 w1 = __half2half2(__float2half(sc * hy * hx));
        __half2 w2 = __half2half2(__float2half(sc * hy * lx));
        __half2 w3 = __half2half2(__float2half(sc * ly * hx));
        __half2 w4 = __half2half2(__float2half(sc * ly * lx));
        uint4 wp;
        wp.x = *(unsigned*)&w1; wp.y = *(unsigned*)&w2;
        wp.z = *(unsigned*)&w3; wp.w = *(unsigned*)&w4;
        s_w[t] = wp;
    }
    __syncthreads();

    const int cofs = h * 128 + 4 * l;    // global channel of lane's first ch
    float* so = s_out + l * NBINS;       // + j*32*NBINS + bin  (c' = j*32+l)

    #pragma unroll 1
    for (int k = 0; k < 3; ++k) {
        const int binA = 16 * k + 2 * w;       // 0..47
        const int binB = binA + 1;

        float a0, a1, a2, a3, b0, b1, b2, b3;
        gather_bin(g, s_base, s_dxe, s_dye, s_w, binA, cofs, a0, a1, a2, a3);
        gather_bin(g, s_base, s_dxe, s_dye, s_w, binB, cofs, b0, b1, b2, b3);

        so[0 * 32 * NBINS + binA] = a0;
        so[1 * 32 * NBINS + binA] = a1;
        so[2 * 32 * NBINS + binA] = a2;
        so[3 * 32 * NBINS + binA] = a3;
        so[0 * 32 * NBINS + binB] = b0;
        so[1 * 32 * NBINS + binB] = b1;
        so[2 * 32 * NBINS + binB] = b2;
        so[3 * 32 * NBINS + binB] = b3;
    }
    if (w == 0) {                              // bin 48 epilogue
        float a0, a1, a2, a3;
        gather_bin(g, s_base, s_dxe, s_dye, s_w, 48, cofs, a0, a1, a2, a3);
        so[0 * 32 * NBINS + 48] = a0;
        so[1 * 32 * NBINS + 48] = a1;
        so[2 * 32 * NBINS + 48] = a2;
        so[3 * 32 * NBINS + 48] = a3;
    }
    __syncthreads();

    // flush 128*49 = 6272 floats, coalesced; invert channel swizzle.
    float* op = out + (size_t)r * (C_ * NBINS) + h * (128 * NBINS);
    #pragma unroll
    for (int j = 0; j < 25; ++j) {
        int idx = j * 256 + t;
        if (j < 24 || t < 128) {
            int c   = idx / NBINS;
            int bin = idx - c * NBINS;
            op[idx] = s_out[((c & 3) * 32 + (c >> 2)) * NBINS + bin];
        }
    }
}

extern "C" void kernel_launch(void* const* d_in, const int* in_sizes, int n_in,
                              void* d_out, int out_size)
{
    const float* feat = (const float*)d_in[0];   // [2,256,200,200] f32
    const float* rois = (const float*)d_in[1];   // [1000,6] f32
    float* out = (float*)d_out;                  // [1000,256,7,7] f32

    int R = in_sizes[1] / 6;

    dim3 tgrid((W_ + 63) / 64, 2 * H_, C_ / 64);
    dim3 tblk(32, 8);
    transpose_kernel<<<tgrid, tblk>>>(feat);

    roi_gather_kernel<<<R * 2, 256>>>(rois, out);
}